// round 1
// baseline (speedup 1.0000x reference)
#include <cuda_runtime.h>
#include <cstddef>

// ---------------------------------------------------------------------------
// Compile-time constants: orthonormal DCT-II matrix and inverse quant table.
// All folded to FP32 immediates by ptxas (FFMA-imm form, rt_SMSP=1).
// ---------------------------------------------------------------------------
__device__ __host__ constexpr float cospi16(int m) {
    // cos(m * pi / 16), exact table for m in [0,8], symmetry elsewhere
    constexpr float t[9] = {
        1.0f,
        0.9807852804032304f, 0.9238795325112867f, 0.8314696123025452f,
        0.7071067811865476f, 0.5555702330196022f, 0.3826834323650898f,
        0.1950903220161283f, 0.0f};
    m %= 32; if (m < 0) m += 32;          // period 2*pi
    if (m > 16) m = 32 - m;               // cos(2pi - x) = cos(x)
    return (m <= 8) ? t[m] : -t[16 - m];  // cos(pi - x) = -cos(x)
}

// C[k][n] = f_k * cos(pi*(2n+1)*k/16), f_0 = 1/sqrt(8), f_k = 1/2
__device__ __host__ constexpr float dctc(int k, int n) {
    return (k == 0 ? 0.3535533905932738f : 0.5f) * cospi16((2 * n + 1) * k);
}

// 1 / (lum[k][l] / 100) = 100 / lum[k][l]
__device__ __host__ constexpr float invq(int k, int l) {
    constexpr int lum[8][8] = {
        {16, 11, 10, 16, 24, 40, 51, 61},
        {12, 12, 14, 19, 26, 58, 60, 55},
        {14, 13, 16, 24, 40, 57, 69, 56},
        {14, 17, 22, 29, 51, 87, 80, 62},
        {18, 22, 37, 56, 68, 109, 103, 77},
        {24, 36, 55, 64, 81, 104, 113, 92},
        {49, 64, 78, 87, 103, 121, 120, 101},
        {72, 92, 95, 98, 112, 100, 103, 99}};
    return 100.0f / (float)lum[k][l];
}

// ---------------------------------------------------------------------------
// One thread per 8x8 block. B=16, H=W=1024, hb=wb=128 -> 262144 threads.
// Layout: tid = (b*128 + h)*128 + w  so adjacent lanes share adjacent w
// (coalesced output STG.32; input LDG.128 pairs stride 32B across lanes).
// ---------------------------------------------------------------------------
__global__ __launch_bounds__(256, 2)
void jpeg_dctq_kernel(const float* __restrict__ img,
                      const float* __restrict__ qf,
                      float* __restrict__ out) {
    const int tid = blockIdx.x * 256 + threadIdx.x;
    const int w = tid & 127;
    const int h = (tid >> 7) & 127;
    const int b = tid >> 14;

    // ---- load 8x8 block (16 x LDG.128, front-batched for MLP) ----
    const float* ip = img + ((size_t)b << 20) + (size_t)(h * 8) * 1024 + w * 8;
    float v[64];
#pragma unroll
    for (int n = 0; n < 8; n++) {
        const float4 q0 = reinterpret_cast<const float4*>(ip + n * 1024)[0];
        const float4 q1 = reinterpret_cast<const float4*>(ip + n * 1024)[1];
        v[n * 8 + 0] = q0.x; v[n * 8 + 1] = q0.y;
        v[n * 8 + 2] = q0.z; v[n * 8 + 3] = q0.w;
        v[n * 8 + 4] = q1.x; v[n * 8 + 5] = q1.y;
        v[n * 8 + 6] = q1.z; v[n * 8 + 7] = q1.w;
    }

    // NOTE: the reference subtracts 128 before the DCT. By linearity that only
    // shifts the DC coefficient: DCT2D(128 * ones) = 1024 at [0][0], 0 elsewhere.
    // We fold it into a single subtraction after the transform.

    // ---- stage 1: vertical DCT (transform n index), in place per column ----
#pragma unroll
    for (int m = 0; m < 8; m++) {
        float a[8];
#pragma unroll
        for (int n = 0; n < 8; n++) a[n] = v[n * 8 + m];
#pragma unroll
        for (int k = 0; k < 8; k++) {
            float acc = dctc(k, 0) * a[0];
#pragma unroll
            for (int n = 1; n < 8; n++) acc = fmaf(dctc(k, n), a[n], acc);
            v[k * 8 + m] = acc;
        }
    }

    // ---- per-batch quantization scale ----
    const float q = qf[b];
    const float invf = (q < 50.0f) ? (q * 0.0002f)           // 1/(5000/q) = q/5000
                                   : (1.0f / (200.0f - 2.0f * q));

    // ---- stage 2: horizontal DCT (transform m index), in place per row ----
#pragma unroll
    for (int k = 0; k < 8; k++) {
        float a[8];
#pragma unroll
        for (int m = 0; m < 8; m++) a[m] = v[k * 8 + m];
#pragma unroll
        for (int l = 0; l < 8; l++) {
            float acc = dctc(l, 0) * a[0];
#pragma unroll
            for (int m = 1; m < 8; m++) acc = fmaf(dctc(l, m), a[m], acc);
            v[k * 8 + l] = acc;
        }
    }

    v[0] -= 1024.0f;  // folded "-128" mean shift (DC term only)

    // ---- quantize + store: out[b, k*8+l, h, w], 64 coalesced STG.32 ----
    float* op = out + ((size_t)b << 20) + h * 128 + w;
#pragma unroll
    for (int i = 0; i < 64; i++)
        op[(size_t)i * 16384] = v[i] * (invf * invq(i >> 3, i & 7));
}

extern "C" void kernel_launch(void* const* d_in, const int* in_sizes, int n_in,
                              void* d_out, int out_size) {
    const float* img = (const float*)d_in[0];   // [16,1,1024,1024] fp32
    const float* qf  = (const float*)d_in[1];   // [16] fp32
    float* out = (float*)d_out;                 // [16,64,128,128] fp32

    // 16*128*128 = 262144 threads, 256/block -> 1024 blocks
    jpeg_dctq_kernel<<<1024, 256>>>(img, qf, out);
}